// round 17
// baseline (speedup 1.0000x reference)
#include <cuda_runtime.h>

#define NS 20480
#define EMAX 120000
#define DHIST 4096
#define MAXB 160
#define DAMAX 64
#define KBW (NS / 32)

__device__ __align__(16) int g_tgtHist[NS + 8];
__device__ __align__(16) int g_curA[NS + 8];        // doubles as srcHist after ph1
__device__ __align__(16) int g_eScat[NS * DAMAX];
__device__ __align__(16) int g_tgtU[NS * DAMAX];
__device__ __align__(16) int g_tgtS[NS * DAMAX];
__device__ __align__(16) int g_prod[NS + 8];
__device__ __align__(16) int g_histTri[NS + 8];
__device__ __align__(16) int g_deg[NS + 8];
__device__ int g_deg2[NS + 8];
__device__ __align__(16) int g_keptOut[NS + 8], g_keptInK[NS + 8];
__device__ __align__(16) int g_cntKept[NS + 8];
__device__ int g_kBase[NS + 8];
__device__ __align__(16) int g_histD[DHIST + 8];
__device__ int g_cumD[DHIST + 8];
__device__ int g_maxNode, g_cursor;
__device__ __align__(16) int g_tieEx[NS + 8];
__device__ __align__(16) unsigned g_keepBits[KBW + 8];
__device__ __align__(16) int g_srcPresent[NS + 8], g_present[NS + 8];
__device__ int g_srcRank[NS + 8], g_rank[NS + 8];
__device__ float g_Wt[3 * 64 * 64];
__device__ __align__(16) float g_Sout[NS * 64];
__device__ volatile int g_arrive[MAXB * 32];
__device__ volatile int g_barPhase;
__device__ volatile int g_mini[8];
__device__ volatile int g_keepReady;

// dynamic smem layout (bytes)
#define OFF_SV    0
#define OFF_UNS   24576
#define OFF_SRT   32768
#define OFF_DN    40960
#define OFF_KO    49152
#define OFF_KR    57344
#define OFF_KB    98304
#define SMEM_TOTAL 100864

__device__ __forceinline__ void gridBar(int ep, int nb) {
    __syncthreads();
    if (blockIdx.x == 0) {
        if (threadIdx.x < 32) {
            int lane = threadIdx.x;
            if (lane == 0) { __threadfence(); g_arrive[0] = ep; }
            bool ok;
            do {
                ok = true;
                for (int s = lane; s < nb; s += 32)
                    if (g_arrive[s * 32] < ep) ok = false;
            } while (__ballot_sync(0xffffffffu, !ok));
            if (lane == 0) { __threadfence(); g_barPhase = ep; }
        }
    } else if (threadIdx.x == 0) {
        __threadfence();
        g_arrive[blockIdx.x * 32] = ep;
        while (g_barPhase < ep) __nanosleep(32);
        __threadfence();
    }
    __syncthreads();
}

__device__ __forceinline__ int blockScanEx(int v, int* tot) {
    __shared__ int s_w[32];
    __shared__ int s_tot;
    int lane = threadIdx.x & 31, wid = threadIdx.x >> 5, nw = blockDim.x >> 5;
    int inc = v;
#pragma unroll
    for (int o = 1; o < 32; o <<= 1) {
        int u = __shfl_up_sync(0xffffffffu, inc, o);
        if (lane >= o) inc += u;
    }
    if (lane == 31) s_w[wid] = inc;
    __syncthreads();
    if (wid == 0) {
        int sv2 = (lane < nw) ? s_w[lane] : 0;
        int si = sv2;
#pragma unroll
        for (int o = 1; o < 32; o <<= 1) {
            int u = __shfl_up_sync(0xffffffffu, si, o);
            if (lane >= o) si += u;
        }
        s_w[lane] = si - sv2;
        if (lane == 31) s_tot = si;
    }
    __syncthreads();
    int ex = inc - v + s_w[wid];
    *tot = s_tot;
    __syncthreads();
    return ex;
}

template <int VPT4>
__device__ void sbScanFast(const int* in, int* out, int n) {
    int v[VPT4 * 4];
    const int4* in4 = (const int4*)in;
#pragma unroll
    for (int j = 0; j < VPT4; j++) {
        int4 q = in4[threadIdx.x * VPT4 + j];
        v[4 * j] = q.x; v[4 * j + 1] = q.y; v[4 * j + 2] = q.z; v[4 * j + 3] = q.w;
    }
    int loc = 0;
#pragma unroll
    for (int j = 0; j < VPT4 * 4; j++) { int t = v[j]; v[j] = loc; loc += t; }
    int tot, ex = blockScanEx(loc, &tot);
    int base = threadIdx.x * VPT4 * 4;
#pragma unroll
    for (int j = 0; j < VPT4 * 4; j++) {
        int i = base + j;
        if (i < n) out[i] = ex + v[j];
    }
    if (threadIdx.x == 0) out[n] = tot;
}

__global__ void kInitAll(const float* __restrict__ W) {
    int i = blockIdx.x * blockDim.x + threadIdx.x;
    int gsz = gridDim.x * blockDim.x;
    for (int j = i; j < MAXB * 32; j += gsz) g_arrive[j] = 0;
    for (int j = i; j < NS; j += gsz) {
        g_tgtHist[j] = 0; g_curA[j] = 0;
        g_histTri[j] = 0; g_deg2[j] = 0;
        g_keptOut[j] = 0; g_keptInK[j] = 0; g_cntKept[j] = 0;
        g_srcPresent[j] = 0; g_present[j] = 0;
    }
    for (int j = i; j < DHIST; j += gsz) g_histD[j] = 0;
    for (int j = i; j < 12288; j += gsz) {
        int o = j & 63, ii = (j >> 6) & 63, k = j >> 12;
        g_Wt[j] = W[o * 192 + ii * 3 + k];
    }
    if (i < 8) g_mini[i] = 0;
    if (i == 0) { g_barPhase = 0; g_maxNode = -1; g_cursor = 0; g_keepReady = 0; }
}

__global__ void __launch_bounds__(1024, 1) kMega(
    const float* __restrict__ x, const int* __restrict__ ei,
    const float* __restrict__ bvec, float* __restrict__ out, int N, int E)
{
    extern __shared__ char dsm[];
    float (*sv)[192]   = (float(*)[192])(dsm + OFF_SV);
    int (*s_uns)[DAMAX] = (int(*)[DAMAX])(dsm + OFF_UNS);
    int (*s_srt)[DAMAX] = (int(*)[DAMAX])(dsm + OFF_SRT);
    int (*s_dn)[DAMAX]  = (int(*)[DAMAX])(dsm + OFF_DN);
    int (*s_ko)[DAMAX]  = (int(*)[DAMAX])(dsm + OFF_KO);
    unsigned short* s_kr = (unsigned short*)(dsm + OFF_KR);
    unsigned* s_kb       = (unsigned*)(dsm + OFF_KB);
    __shared__ int s_red[32];
    __shared__ int s_dstar, s_r;
    const int tid = threadIdx.x, bid = blockIdx.x, nb = gridDim.x;
    const int gsz = nb * 1024;
    const int g0 = bid * 1024 + tid;
    const int lane = tid & 31, w = tid >> 5;
    const int warpId = g0 >> 5, nwarps = nb * 32;
    int ep = 0;

    // ---- ph1: tgt histogram + bucket scatter ----
    for (int e = g0; e < E; e += gsz) {
        int s = ei[e], t = ei[E + e];
        atomicAdd(&g_tgtHist[t], 1);
        int slot = atomicAdd(&g_curA[s], 1);
        if (slot < DAMAX) {
            g_eScat[s * DAMAX + slot] = e;
            g_tgtU[s * DAMAX + slot] = t;
        }
    }
    gridBar(++ep, nb);

    // ---- ph2: warp-per-node: histTri + deg2 scatter ----
    for (int s = warpId; s < N; s += nwarps) {
        int da = g_curA[s];
        if (da == 0) continue;
        int dc = da > DAMAX ? DAMAX : da;
        int lo = s * DAMAX;
        int ih = g_tgtHist[s];
        int acc = 0;
        for (int i = lane; i < dc; i += 32) {
            int t = g_tgtU[lo + i];
            acc += g_curA[t];
            atomicAdd(&g_deg2[t], ih);
        }
#pragma unroll
        for (int o = 16; o; o >>= 1) acc += __shfl_down_sync(0xffffffffu, acc, o);
        if (lane == 0) g_histTri[s] = acc;
    }
    gridBar(++ep, nb);

    // ---- ph3 (merged): deg+histD+maxNode (blocks 0-7); b0: median chain + keep
    //      bitmap + keepReady flag; blocks 1+: bucket stable sort; THEN all
    //      blocks spin on keepReady and run keptOut/keptInK on UNSORTED buckets ----
    if (bid < 8) {
        int chunk = (N + 7) / 8;
        int lo3 = bid * chunk, hi3 = lo3 + chunk; if (hi3 > N) hi3 = N;
        int mloc = -1;
        for (int i = lo3 + tid; i < hi3; i += 1024) {
            int d = g_histTri[i] + g_curA[i] * g_tgtHist[i] + g_deg2[i];
            g_deg[i] = d;
            int dd = d > DHIST - 1 ? DHIST - 1 : d;
            atomicAdd(&g_histD[dd], 1);
            if (d > 0 && i > mloc) mloc = i;
        }
#pragma unroll
        for (int o = 16; o; o >>= 1) {
            int u = __shfl_down_sync(0xffffffffu, mloc, o);
            if (u > mloc) mloc = u;
        }
        if (lane == 0) s_red[w] = mloc;
        __syncthreads();
        if (tid < 32) {
            int m = s_red[tid];
#pragma unroll
            for (int o = 16; o; o >>= 1) {
                int u = __shfl_down_sync(0xffffffffu, m, o);
                if (u > m) m = u;
            }
            if (tid == 0 && m >= 0) atomicMax(&g_maxNode, m);
        }
        __syncthreads();
        if (tid == 0) { __threadfence(); g_mini[bid] = 1; }
    }
    if (bid == 0) {
        if (tid == 0) {
            bool ok;
            do {
                ok = true;
                for (int s = 0; s < 8; s++) if (g_mini[s] == 0) ok = false;
            } while (!ok);
            __threadfence();
        }
        __syncthreads();
        sbScanFast<1>(g_histD, g_cumD, DHIST);
        __syncthreads();
        int L = g_maxNode + 1, half = L >> 1;
        int extra = N - L;
        for (int d = tid; d < DHIST; d += 1024) {
            int lo2 = g_cumD[d] - (d > 0 ? extra : 0);
            int hi2 = g_cumD[d + 1] - extra;
            if (lo2 <= half && half < hi2) { s_dstar = d; s_r = half - lo2; }
        }
        __syncthreads();
        int dstar = s_dstar, r = s_r;
        for (int i = tid; i < NS; i += 1024)
            g_prod[i] = (i < L && g_deg[i] == dstar) ? 1 : 0;
        __syncthreads();
        sbScanFast<5>(g_prod, g_tieEx, N);
        __syncthreads();
        for (int i = tid; i < NS; i += 1024) {
            int kp = 0;
            if (i < N) {
                kp = 1;
                if (i < L) {
                    int d = g_deg[i];
                    if (d < dstar) kp = 0;
                    else if (d == dstar && g_tieEx[i] < r) kp = 0;
                }
            }
            unsigned bits = __ballot_sync(0xffffffffu, kp);
            if (lane == 0) g_keepBits[i >> 5] = bits;
        }
        __syncthreads();
        if (tid == 0) { __threadfence(); g_keepReady = 1; }
    } else {
        int warpId1 = ((bid - 1) * 1024 + tid) >> 5, nwarps1 = (nb - 1) * 32;
        for (int v = warpId1; v < N; v += nwarps1) {
            int s = g_curA[v];
            if (s == 0) continue;
            int dc = s > DAMAX ? DAMAX : s;
            int lo = v * DAMAX;
            for (int i = lane; i < dc; i += 32) s_uns[w][i] = g_eScat[lo + i];
            __syncwarp();
            for (int i = lane; i < dc; i += 32) {
                int val = s_uns[w][i], r = 0;
                for (int j = 0; j < dc; j++) r += (s_uns[w][j] < val);
                g_tgtS[lo + r] = g_tgtU[lo + i];
            }
            __syncwarp();
        }
    }
    // all blocks: wait for keep bitmap, load to shared, then keptOut/keptInK
    if (tid == 0) { while (g_keepReady == 0) __nanosleep(32); __threadfence(); }
    __syncthreads();
    for (int j = tid; j < KBW; j += 1024) s_kb[j] = g_keepBits[j];
    __syncthreads();
#define KEEPB(i) ((s_kb[(i) >> 5] >> ((i) & 31)) & 1u)
    for (int s = warpId; s < N; s += nwarps) {
        if (!KEEPB(s)) continue;
        int da = g_curA[s];
        if (da == 0) continue;
        int dc = da > DAMAX ? DAMAX : da;
        int lo = s * DAMAX;
        int kcnt = 0;
        for (int c0 = 0; c0 < dc; c0 += 32) {
            int rem = dc - c0; if (rem > 32) rem = 32;
            int t = 0, kp = 0;
            if (lane < rem) { t = g_tgtU[lo + c0 + lane]; kp = KEEPB(t); }
            unsigned mask = __ballot_sync(0xffffffffu, kp);
            kcnt += __popc(mask);
            if (kp) atomicAdd(&g_keptInK[t], 1);
        }
        if (lane == 0) g_keptOut[s] = kcnt;
    }
    gridBar(++ep, nb);

    // ---- ph4: warp-per-kept-node: cntKept + present flags + fused Sout ----
    for (int s = warpId; s < N; s += nwarps) {
        if (!KEEPB(s)) continue;
        int da = g_curA[s];
        int dc = da > DAMAX ? DAMAX : da;
        int lo = s * DAMAX;
        int cnt = 0;
        int sInK = g_keptInK[s];
        float2 aS = make_float2(0.f, 0.f);
        unsigned anyM = 0;
        for (int c0 = 0; c0 < dc; c0 += 32) {
            int rem = dc - c0; if (rem > 32) rem = 32;
            int t = 0, kp = 0;
            if (lane < rem) { t = g_tgtS[lo + c0 + lane]; kp = KEEPB(t); }
            if (kp) {
                cnt += g_keptOut[t];
                if (sInK) g_present[t] = 1;
            }
            unsigned mask = __ballot_sync(0xffffffffu, kp);
            anyM |= mask;
            while (mask) {
                int j = __ffs(mask) - 1; mask &= mask - 1;
                int tj = __shfl_sync(0xffffffffu, t, j);
                float2 xx = ((const float2*)(x + tj * 64))[lane];
                aS.x += xx.x; aS.y += xx.y;
            }
        }
        if (anyM) ((float2*)(g_Sout + s * 64))[lane] = aS;
#pragma unroll
        for (int o = 16; o; o >>= 1) cnt += __shfl_down_sync(0xffffffffu, cnt, o);
        cnt = __shfl_sync(0xffffffffu, cnt, 0);
        if (lane == 0) {
            g_cntKept[s] = cnt;
            if (cnt > 0) { g_present[s] = 1; g_srcPresent[s] = 1; }
            if (g_keptOut[s] && sInK) g_present[s] = 1;
        }
    }
    gridBar(++ep, nb);

    // ---- ph5: three scans on three blocks ----
    if (bid == 0) sbScanFast<5>(g_cntKept, g_kBase, N);
    else if (bid == 1) sbScanFast<5>(g_srcPresent, g_srcRank, N);
    else if (bid == 2) sbScanFast<5>(g_present, g_rank, N);
    gridBar(++ep, nb);

    // build packed keep|rank table (rank < 2^15)
    for (int i = tid; i < N; i += 1024)
        s_kr[i] = (unsigned short)((KEEPB(i) << 15) | (unsigned)g_rank[i]);
    __syncthreads();

    // ---- ph6 (final): fused generation + new_ei + factored segment compute ----
    {
        int U = g_srcRank[N], P = g_kBase[N];
        int obase = 64 * U;
        for (;;) {
            int base;
            if (lane == 0) base = atomicAdd(&g_cursor, 4);
            base = __shfl_sync(0xffffffffu, base, 0);
            if (base >= N) break;
            for (int a = base; a < base + 4 && a < N; a++) {
                int cnt = g_cntKept[a];
                if (!cnt) continue;
                int da = g_curA[a];
                int dc = da > DAMAX ? DAMAX : da;
                int lo = a * DAMAX;
                for (int i = lane; i < dc; i += 32) s_uns[w][i] = g_tgtS[lo + i];
                __syncwarp();
                for (int i = lane; i < dc; i += 32) {
                    int vi = s_uns[w][i], r = 0;
                    for (int j = 0; j < dc; j++) {
                        int vj = s_uns[w][j];
                        r += (vj < vi) | ((vj == vi) & (j < i));
                    }
                    s_srt[w][r] = vi;
                }
                __syncwarp();
                for (int i = lane; i < dc; i += 32) {
                    int v = s_srt[w][i];
                    int dn = g_curA[v];
                    s_dn[w][i] = dn > DAMAX ? DAMAX : dn;
                    s_ko[w][i] = (s_kr[v] >> 15) ? g_keptOut[v] : 0;
                }
                __syncwarp();
                int u = g_srcRank[a];
                float ra = (float)(s_kr[a] & 0x7fffu);
                int p = g_kBase[a];
                float2 aB = make_float2(0.f, 0.f), aC = make_float2(0.f, 0.f);
                int idx = 0;
                while (idx < dc) {
                    int v = s_srt[w][idx];
                    int k = 1;
                    while (idx + k < dc && s_srt[w][idx + k] == v) k++;
                    int ko = s_ko[w][idx];
                    if (ko) {
                        float kf = (float)k;
                        float m = kf * (float)ko;
                        float2 xv = ((const float2*)(x + v * 64))[lane];
                        float2 so = ((const float2*)(g_Sout + v * 64))[lane];
                        aB.x += m * xv.x; aB.y += m * xv.y;
                        aC.x += kf * so.x; aC.y += kf * so.y;
                        int eb = v * DAMAX, din = s_dn[w][idx];
                        float rv = (float)(s_kr[v] & 0x7fffu);
                        for (int c0 = 0; c0 < din; c0 += 32) {
                            int rem = din - c0; if (rem > 32) rem = 32;
                            int wv = 0, kp = 0;
                            unsigned short krw = 0;
                            if (lane < rem) {
                                wv = g_tgtS[eb + c0 + lane];
                                krw = s_kr[wv];
                                kp = krw >> 15;
                            }
                            unsigned mask = __ballot_sync(0xffffffffu, kp);
                            int j = __popc(mask & ((1u << lane) - 1u));
                            if (kp) {
                                float rw = (float)(krw & 0x7fffu);
                                for (int c = 0; c < k; c++) {
                                    int pp = p + j * k + c;
                                    out[obase + pp] = ra;
                                    out[obase + P + pp] = rv;
                                    out[obase + 2 * P + pp] = rw;
                                }
                            }
                            p += k * __popc(mask);
                        }
                    }
                    idx += k;
                }
                float inv = 1.0f / (float)cnt;
                float2 xa = ((const float2*)(x + a * 64))[lane];
                sv[w][2 * lane] = xa.x;              sv[w][2 * lane + 1] = xa.y;
                sv[w][64 + 2 * lane] = aB.x * inv;   sv[w][64 + 2 * lane + 1] = aB.y * inv;
                sv[w][128 + 2 * lane] = aC.x * inv;  sv[w][128 + 2 * lane + 1] = aC.y * inv;
                __syncwarp();
                float acc0 = bvec[lane], acc1 = bvec[lane + 32];
#pragma unroll 8
                for (int i = 0; i < 64; i++) {
                    float v0 = sv[w][i], v1 = sv[w][64 + i], v2 = sv[w][128 + i];
                    int bb = i * 64 + lane;
                    acc0 += g_Wt[bb] * v0 + g_Wt[4096 + bb] * v1 + g_Wt[8192 + bb] * v2;
                    acc1 += g_Wt[bb + 32] * v0 + g_Wt[4096 + bb + 32] * v1 + g_Wt[8192 + bb + 32] * v2;
                }
                out[u * 64 + lane] = acc0;
                out[u * 64 + lane + 32] = acc1;
                __syncwarp();
            }
        }
    }
}

extern "C" void kernel_launch(void* const* d_in, const int* in_sizes, int n_in,
                              void* d_out, int out_size) {
    const float* x = (const float*)d_in[0];
    const int* ei = (const int*)d_in[1];
    const float* W = (const float*)d_in[2];
    const float* b = (const float*)d_in[3];
    float* out = (float*)d_out;
    int N = in_sizes[0] / 64;
    int E = in_sizes[1] / 2;

    int dev = 0, sms = 148;
    cudaGetDevice(&dev);
    cudaDeviceGetAttribute(&sms, cudaDevAttrMultiProcessorCount, dev);
    if (sms > MAXB) sms = MAXB;

    cudaFuncSetAttribute(kMega, cudaFuncAttributeMaxDynamicSharedMemorySize, SMEM_TOTAL);
    kInitAll<<<64, 256>>>(W);
    kMega<<<sms, 1024, SMEM_TOTAL>>>(x, ei, b, out, N, E);
}